// round 6
// baseline (speedup 1.0000x reference)
#include <cuda_runtime.h>
#include <stdint.h>

#define N_NODES 100000
#define N_EDGES 800000
#define HIDDEN  128

// ---------------- scratch (static device memory; no allocation) -------------
__device__ float g_S1[(size_t)N_NODES * HIDDEN];
__device__ float g_S2[(size_t)N_NODES * HIDDEN];
__device__ int   g_d1[N_NODES];
__device__ int   g_d2[N_NODES];

// ---------------- helpers ---------------------------------------------------
__device__ __forceinline__ float2 unpack2(unsigned long long v) {
    float2 f;
    asm("mov.b64 {%0, %1}, %2;" : "=f"(f.x), "=f"(f.y) : "l"(v));
    return f;
}
__device__ __forceinline__ void fma2(unsigned long long& acc,
                                     unsigned long long a,
                                     unsigned long long b) {
    asm("fma.rn.f32x2 %0, %1, %2, %0;" : "+l"(acc) : "l"(a), "l"(b));
}

// ---------------- kernel 1: zero scratch ------------------------------------
__global__ void zero_kernel() {
    size_t tid    = (size_t)blockIdx.x * blockDim.x + threadIdx.x;
    size_t stride = (size_t)gridDim.x * blockDim.x;
    const size_t n4 = (size_t)N_NODES * HIDDEN / 4;
    float4 z = make_float4(0.f, 0.f, 0.f, 0.f);
    for (size_t j = tid; j < n4; j += stride) {
        ((float4*)g_S1)[j] = z;
        ((float4*)g_S2)[j] = z;
    }
    for (size_t j = tid; j < N_NODES; j += stride) {
        g_d1[j] = 0;
        g_d2[j] = 0;
    }
}

// ---------------- kernel 2: fused edge aggregation (one warp per edge) ------
__global__ void __launch_bounds__(256) edge_kernel(const float* __restrict__ h,
                                                   const int*   __restrict__ esrc,
                                                   const int*   __restrict__ edst) {
    int warp = (blockIdx.x * blockDim.x + threadIdx.x) >> 5;
    int lane = threadIdx.x & 31;
    if (warp >= N_EDGES) return;

    int s = esrc[warp];
    int d = edst[warp];

    float4 vd = ((const float4*)(h + (size_t)d * HIDDEN))[lane];
    float4 vs = ((const float4*)(h + (size_t)s * HIDDEN))[lane];

    atomicAdd(((float4*)(g_S1 + (size_t)s * HIDDEN)) + lane, vd);
    atomicAdd(((float4*)(g_S2 + (size_t)d * HIDDEN)) + lane, vs);

    if (lane == 0)      atomicAdd(&g_d1[s], 1);
    else if (lane == 1) atomicAdd(&g_d2[d], 1);
}

// ---------------- kernel 3: FFMA2 GEMM + bias + relu ------------------------
// Block tile 128 rows x 128 cols, 256 threads (ty=tid>>4 row group, tx=tid&15
// col group), thread tile 8x8 as 4 row-pairs x 8 cols of f32x2 accumulators.
// smem layouts are pre-paired so every FFMA2 operand is a direct LDS.128 half:
//   As (16 KB): per kk, row-pair p packed (r2p, r2p+1); float idx =
//       kk*128 + ((r>>2)&1)*64 + (r>>3)*4 + (r&3)
//   Wd (32 KB): per kk, col c stored as splat pair (w,w); float idx =
//       kk*256 + ((c&7)>>1)*64 + (c>>3)*4 + (c&1)*2
// Reads: A float4 #(kk*32 + q*16 + ty)  (q=0,1)  -> row-pairs ty*4+2q, +1
//        W float4 #(kk*64 + q*16 + tx)  (q=0..3) -> splat cols tx*8+2q, +1
// Both reads are 256B-contiguous across the warp -> conflict-free.
__global__ void __launch_bounds__(256, 2)
gemm_kernel(const float* __restrict__ h,
            const float* __restrict__ Ww,
            const float* __restrict__ Wb,
            const float* __restrict__ Wsw,
            const float* __restrict__ Wsb,
            const float* __restrict__ Wtw,
            const float* __restrict__ Wtb,
            float* __restrict__ out) {
    __shared__ __align__(16) float As[32 * 128];   // 16384 B
    __shared__ __align__(16) float Wd[32 * 256];   // 32768 B

    const int tid  = threadIdx.x;
    const int tx   = tid & 15;          // cols tx*8 .. tx*8+7
    const int ty   = tid >> 4;          // rows ty*8 .. ty*8+7
    const int row0 = blockIdx.x * 128;

    const float* Alist[3];
    Alist[0] = g_S1; Alist[1] = h; Alist[2] = g_S2;
    const float* Wlist[3];
    Wlist[0] = Ww; Wlist[1] = Wsw; Wlist[2] = Wtw;

    unsigned long long acc[4][8];       // [row-pair][col]
#pragma unroll
    for (int p = 0; p < 4; ++p)
#pragma unroll
        for (int c = 0; c < 8; ++c) acc[p][c] = 0ull;

    const ulonglong2* Asu = (const ulonglong2*)As;
    const ulonglong2* Wdu = (const ulonglong2*)Wd;

#pragma unroll 1
    for (int ch = 0; ch < 12; ++ch) {
        const int sidx = ch >> 2;
        const int k0   = (ch & 3) * 32;
        const float* A = Alist[sidx];
        const float* W = Wlist[sidx];

        __syncthreads();
        // ---- stage A: 128 rows x 32 k (1024 float4, 4/thread) ----
#pragma unroll
        for (int i = 0; i < 4; ++i) {
            int idx = tid + i * 256;          // 0..1023
            int r   = idx >> 3;               // 0..127
            int f4  = idx & 7;
            float4 v = make_float4(0.f, 0.f, 0.f, 0.f);
            int grow = row0 + r;
            if (grow < N_NODES)
                v = *(const float4*)(A + (size_t)grow * HIDDEN + k0 + f4 * 4);
            int base = ((r >> 2) & 1) * 64 + (r >> 3) * 4 + (r & 3);
            As[(f4 * 4 + 0) * 128 + base] = v.x;
            As[(f4 * 4 + 1) * 128 + base] = v.y;
            As[(f4 * 4 + 2) * 128 + base] = v.z;
            As[(f4 * 4 + 3) * 128 + base] = v.w;
        }
        // ---- stage W: 128 cols x 32 k, splat-duplicated ----
#pragma unroll
        for (int i = 0; i < 4; ++i) {
            int idx = tid + i * 256;
            int c   = idx >> 3;               // output col 0..127
            int f4  = idx & 7;
            float4 v = *(const float4*)(W + (size_t)c * HIDDEN + k0 + f4 * 4);
            int base = ((c & 7) >> 1) * 64 + (c >> 3) * 4 + (c & 1) * 2;
            *(float2*)&Wd[(f4 * 4 + 0) * 256 + base] = make_float2(v.x, v.x);
            *(float2*)&Wd[(f4 * 4 + 1) * 256 + base] = make_float2(v.y, v.y);
            *(float2*)&Wd[(f4 * 4 + 2) * 256 + base] = make_float2(v.z, v.z);
            *(float2*)&Wd[(f4 * 4 + 3) * 256 + base] = make_float2(v.w, v.w);
        }
        __syncthreads();

        // ---- compute: 32 kk, 32 FFMA2 + 6 LDS.128 per kk ----
#pragma unroll
        for (int kk = 0; kk < 32; ++kk) {
            ulonglong2 a0 = Asu[kk * 32 + ty];        // row-pairs 0,1
            ulonglong2 a1 = Asu[kk * 32 + 16 + ty];   // row-pairs 2,3
            ulonglong2 w0 = Wdu[kk * 64 + tx];        // cols 0,1 (splat)
            ulonglong2 w1 = Wdu[kk * 64 + 16 + tx];   // cols 2,3
            ulonglong2 w2 = Wdu[kk * 64 + 32 + tx];   // cols 4,5
            ulonglong2 w3 = Wdu[kk * 64 + 48 + tx];   // cols 6,7

            fma2(acc[0][0], a0.x, w0.x); fma2(acc[0][1], a0.x, w0.y);
            fma2(acc[0][2], a0.x, w1.x); fma2(acc[0][3], a0.x, w1.y);
            fma2(acc[0][4], a0.x, w2.x); fma2(acc[0][5], a0.x, w2.y);
            fma2(acc[0][6], a0.x, w3.x); fma2(acc[0][7], a0.x, w3.y);
            fma2(acc[1][0], a0.y, w0.x); fma2(acc[1][1], a0.y, w0.y);
            fma2(acc[1][2], a0.y, w1.x); fma2(acc[1][3], a0.y, w1.y);
            fma2(acc[1][4], a0.y, w2.x); fma2(acc[1][5], a0.y, w2.y);
            fma2(acc[1][6], a0.y, w3.x); fma2(acc[1][7], a0.y, w3.y);
            fma2(acc[2][0], a1.x, w0.x); fma2(acc[2][1], a1.x, w0.y);
            fma2(acc[2][2], a1.x, w1.x); fma2(acc[2][3], a1.x, w1.y);
            fma2(acc[2][4], a1.x, w2.x); fma2(acc[2][5], a1.x, w2.y);
            fma2(acc[2][6], a1.x, w3.x); fma2(acc[2][7], a1.x, w3.y);
            fma2(acc[3][0], a1.y, w0.x); fma2(acc[3][1], a1.y, w0.y);
            fma2(acc[3][2], a1.y, w1.x); fma2(acc[3][3], a1.y, w1.y);
            fma2(acc[3][4], a1.y, w2.x); fma2(acc[3][5], a1.y, w2.y);
            fma2(acc[3][6], a1.y, w3.x); fma2(acc[3][7], a1.y, w3.y);
        }
    }

    // ---- epilogue: degree-scaled bias + relu ----
    const int cb = tx * 8;
    float4 bw0 = *(const float4*)(Wb  + cb);
    float4 bw1 = *(const float4*)(Wb  + cb + 4);
    float4 bs0 = *(const float4*)(Wsb + cb);
    float4 bs1 = *(const float4*)(Wsb + cb + 4);
    float4 bt0 = *(const float4*)(Wtb + cb);
    float4 bt1 = *(const float4*)(Wtb + cb + 4);

#pragma unroll
    for (int p = 0; p < 4; ++p) {
        float2 v[8];
#pragma unroll
        for (int c = 0; c < 8; ++c) v[c] = unpack2(acc[p][c]);
#pragma unroll
        for (int hh = 0; hh < 2; ++hh) {
            int r = row0 + ty * 8 + 2 * p + hh;
            if (r >= N_NODES) continue;
            float f1 = (float)g_d1[r];
            float f2 = (float)g_d2[r];
            float4 o0, o1;
            float a0 = hh ? v[0].y : v[0].x;
            float a1 = hh ? v[1].y : v[1].x;
            float a2 = hh ? v[2].y : v[2].x;
            float a3 = hh ? v[3].y : v[3].x;
            float a4 = hh ? v[4].y : v[4].x;
            float a5 = hh ? v[5].y : v[5].x;
            float a6 = hh ? v[6].y : v[6].x;
            float a7 = hh ? v[7].y : v[7].x;
            o0.x = fmaxf(a0 + f1 * bw0.x + bs0.x + f2 * bt0.x, 0.f);
            o0.y = fmaxf(a1 + f1 * bw0.y + bs0.y + f2 * bt0.y, 0.f);
            o0.z = fmaxf(a2 + f1 * bw0.z + bs0.z + f2 * bt0.z, 0.f);
            o0.w = fmaxf(a3 + f1 * bw0.w + bs0.w + f2 * bt0.w, 0.f);
            o1.x = fmaxf(a4 + f1 * bw1.x + bs1.x + f2 * bt1.x, 0.f);
            o1.y = fmaxf(a5 + f1 * bw1.y + bs1.y + f2 * bt1.y, 0.f);
            o1.z = fmaxf(a6 + f1 * bw1.z + bs1.z + f2 * bt1.z, 0.f);
            o1.w = fmaxf(a7 + f1 * bw1.w + bs1.w + f2 * bt1.w, 0.f);
            *(float4*)(out + (size_t)r * HIDDEN + cb)     = o0;
            *(float4*)(out + (size_t)r * HIDDEN + cb + 4) = o1;
        }
    }
}

// ---------------- launch -----------------------------------------------------
extern "C" void kernel_launch(void* const* d_in, const int* in_sizes, int n_in,
                              void* d_out, int out_size) {
    const float* h    = (const float*)d_in[0];
    const int*   esrc = (const int*)  d_in[1];
    const int*   edst = (const int*)  d_in[2];
    const float* Ww   = (const float*)d_in[3];
    const float* Wb   = (const float*)d_in[4];
    const float* Wsw  = (const float*)d_in[5];
    const float* Wsb  = (const float*)d_in[6];
    const float* Wtw  = (const float*)d_in[7];
    const float* Wtb  = (const float*)d_in[8];
    float* out = (float*)d_out;

    zero_kernel<<<2048, 256>>>();
    edge_kernel<<<(N_EDGES + 7) / 8, 256>>>(h, esrc, edst);
    gemm_kernel<<<(N_NODES + 127) / 128, 256>>>(h, Ww, Wb, Wsw, Wsb, Wtw, Wtb, out);
}

// round 7
// speedup vs baseline: 1.0757x; 1.0757x over previous
#include <cuda_runtime.h>
#include <stdint.h>

#define N_NODES 100000
#define N_EDGES 800000
#define HIDDEN  128

// ---------------- scratch (static device memory; no allocation) -------------
__device__ float g_S1[(size_t)N_NODES * HIDDEN];
__device__ float g_S2[(size_t)N_NODES * HIDDEN];
__device__ int   g_d1[N_NODES];
__device__ int   g_d2[N_NODES];

// ---------------- helpers ---------------------------------------------------
__device__ __forceinline__ unsigned long long pack2(float lo, float hi) {
    unsigned long long r;
    asm("mov.b64 %0, {%1, %2};" : "=l"(r) : "f"(lo), "f"(hi));
    return r;
}
__device__ __forceinline__ float2 unpack2(unsigned long long v) {
    float2 f;
    asm("mov.b64 {%0, %1}, %2;" : "=f"(f.x), "=f"(f.y) : "l"(v));
    return f;
}
__device__ __forceinline__ void fma2(unsigned long long& acc,
                                     unsigned long long a,
                                     unsigned long long b) {
    asm("fma.rn.f32x2 %0, %1, %2, %0;" : "+l"(acc) : "l"(a), "l"(b));
}

// ---------------- kernel 1: zero scratch ------------------------------------
__global__ void zero_kernel() {
    size_t tid    = (size_t)blockIdx.x * blockDim.x + threadIdx.x;
    size_t stride = (size_t)gridDim.x * blockDim.x;
    const size_t n4 = (size_t)N_NODES * HIDDEN / 4;
    float4 z = make_float4(0.f, 0.f, 0.f, 0.f);
    for (size_t j = tid; j < n4; j += stride) {
        ((float4*)g_S1)[j] = z;
        ((float4*)g_S2)[j] = z;
    }
    for (size_t j = tid; j < N_NODES; j += stride) {
        g_d1[j] = 0;
        g_d2[j] = 0;
    }
}

// ---------------- kernel 2: fused edge aggregation (one warp per edge) ------
__global__ void __launch_bounds__(256) edge_kernel(const float* __restrict__ h,
                                                   const int*   __restrict__ esrc,
                                                   const int*   __restrict__ edst) {
    int warp = (blockIdx.x * blockDim.x + threadIdx.x) >> 5;
    int lane = threadIdx.x & 31;
    if (warp >= N_EDGES) return;

    int s = esrc[warp];
    int d = edst[warp];

    float4 vd = ((const float4*)(h + (size_t)d * HIDDEN))[lane];
    float4 vs = ((const float4*)(h + (size_t)s * HIDDEN))[lane];

    atomicAdd(((float4*)(g_S1 + (size_t)s * HIDDEN)) + lane, vd);
    atomicAdd(((float4*)(g_S2 + (size_t)d * HIDDEN)) + lane, vs);

    if (lane == 0)      atomicAdd(&g_d1[s], 1);
    else if (lane == 1) atomicAdd(&g_d2[d], 1);
}

// ---------------- kernel 3: FFMA2 GEMM, double-buffered smem ----------------
// Geometry identical to the measured-best core: 64 rows x 128 cols per block,
// 256 threads, thread tile 8 rows x 4 cols of f32x2 accumulators.
// Dynamic smem: As0[32][68], As1[32][68], Ws0[32][132], Ws1[32][132] = 51200 B.
// Per chunk: LDG next->regs, compute current buf, STS regs->other buf, 1 sync.
#define AS_FLOATS (32 * 68)     // 2176
#define WS_FLOATS (32 * 132)    // 4224
#define SMEM_BYTES ((2 * (AS_FLOATS + WS_FLOATS)) * 4)   // 51200

__global__ void __launch_bounds__(256, 2)
gemm_kernel(const float* __restrict__ h,
            const float* __restrict__ Ww,
            const float* __restrict__ Wb,
            const float* __restrict__ Wsw,
            const float* __restrict__ Wsb,
            const float* __restrict__ Wtw,
            const float* __restrict__ Wtb,
            float* __restrict__ out) {
    extern __shared__ float smem[];
    float* AsB[2];
    float* WsB[2];
    AsB[0] = smem;
    AsB[1] = smem + AS_FLOATS;
    WsB[0] = smem + 2 * AS_FLOATS;
    WsB[1] = smem + 2 * AS_FLOATS + WS_FLOATS;

    const int tid  = threadIdx.x;
    const int tx   = tid & 31;      // cols tx*4 .. tx*4+3
    const int ty   = tid >> 5;      // rows ty*8 .. ty*8+7
    const int row0 = blockIdx.x * 64;

    const float* Alist[3];
    Alist[0] = g_S1; Alist[1] = h; Alist[2] = g_S2;
    const float* Wlist[3];
    Wlist[0] = Ww; Wlist[1] = Wsw; Wlist[2] = Wtw;

    // fixed per-thread staging coordinates
    int ar[2], ag[2], arow_ok[2];
#pragma unroll
    for (int j = 0; j < 2; ++j) {
        int lin = tid + j * 256;
        ar[j] = lin >> 3;               // 0..63
        ag[j] = lin & 7;
        arow_ok[j] = (row0 + ar[j]) < N_NODES;
    }
    int wc[4], wg[4];
#pragma unroll
    for (int j = 0; j < 4; ++j) {
        int lin = tid + j * 256;
        wc[j] = lin >> 3;               // 0..127
        wg[j] = lin & 7;
    }

    unsigned long long acc[4][4];
#pragma unroll
    for (int p = 0; p < 4; ++p)
#pragma unroll
        for (int c = 0; c < 4; ++c) acc[p][c] = 0ull;

    float4 pa[2], pw[4];

    // ---- stage chunk 0 into buffer 0 ----
    {
        const float* A = Alist[0];
        const float* W = Wlist[0];
#pragma unroll
        for (int j = 0; j < 2; ++j) {
            pa[j] = make_float4(0.f, 0.f, 0.f, 0.f);
            if (arow_ok[j])
                pa[j] = *(const float4*)(A + (size_t)(row0 + ar[j]) * HIDDEN + ag[j] * 4);
        }
#pragma unroll
        for (int j = 0; j < 4; ++j)
            pw[j] = *(const float4*)(W + (size_t)wc[j] * HIDDEN + wg[j] * 4);

        float* As = AsB[0];
        float* Ws = WsB[0];
#pragma unroll
        for (int j = 0; j < 2; ++j) {
            int kk = ag[j] * 4, r = ar[j];
            As[(kk + 0) * 68 + r] = pa[j].x;
            As[(kk + 1) * 68 + r] = pa[j].y;
            As[(kk + 2) * 68 + r] = pa[j].z;
            As[(kk + 3) * 68 + r] = pa[j].w;
        }
#pragma unroll
        for (int j = 0; j < 4; ++j) {
            int kk = wg[j] * 4, c = wc[j];
            Ws[(kk + 0) * 132 + c] = pw[j].x;
            Ws[(kk + 1) * 132 + c] = pw[j].y;
            Ws[(kk + 2) * 132 + c] = pw[j].z;
            Ws[(kk + 3) * 132 + c] = pw[j].w;
        }
    }
    __syncthreads();

#pragma unroll 1
    for (int ch = 0; ch < 12; ++ch) {
        const int buf = ch & 1;
        const float* As = AsB[buf];
        const float* Ws = WsB[buf];

        // issue next-chunk LDGs first (latency hidden under compute)
        if (ch < 11) {
            int nc   = ch + 1;
            int sidx = nc >> 2;
            int k0   = (nc & 3) * 32;
            const float* A = Alist[sidx];
            const float* W = Wlist[sidx];
#pragma unroll
            for (int j = 0; j < 2; ++j) {
                pa[j] = make_float4(0.f, 0.f, 0.f, 0.f);
                if (arow_ok[j])
                    pa[j] = *(const float4*)(A + (size_t)(row0 + ar[j]) * HIDDEN + k0 + ag[j] * 4);
            }
#pragma unroll
            for (int j = 0; j < 4; ++j)
                pw[j] = *(const float4*)(W + (size_t)wc[j] * HIDDEN + k0 + wg[j] * 4);
        }

        // compute current buffer
#pragma unroll
        for (int kk = 0; kk < 32; ++kk) {
            ulonglong2 a01 = *(const ulonglong2*)&As[kk * 68 + ty * 8];
            ulonglong2 a23 = *(const ulonglong2*)&As[kk * 68 + ty * 8 + 4];
            float4 w = *(const float4*)&Ws[kk * 132 + tx * 4];
            unsigned long long w0 = pack2(w.x, w.x);
            unsigned long long w1 = pack2(w.y, w.y);
            unsigned long long w2 = pack2(w.z, w.z);
            unsigned long long w3 = pack2(w.w, w.w);

            fma2(acc[0][0], a01.x, w0); fma2(acc[0][1], a01.x, w1);
            fma2(acc[0][2], a01.x, w2); fma2(acc[0][3], a01.x, w3);
            fma2(acc[1][0], a01.y, w0); fma2(acc[1][1], a01.y, w1);
            fma2(acc[1][2], a01.y, w2); fma2(acc[1][3], a01.y, w3);
            fma2(acc[2][0], a23.x, w0); fma2(acc[2][1], a23.x, w1);
            fma2(acc[2][2], a23.x, w2); fma2(acc[2][3], a23.x, w3);
            fma2(acc[3][0], a23.y, w0); fma2(acc[3][1], a23.y, w1);
            fma2(acc[3][2], a23.y, w2); fma2(acc[3][3], a23.y, w3);
        }

        // store next chunk into the other buffer, then single sync
        if (ch < 11) {
            float* Asn = AsB[buf ^ 1];
            float* Wsn = WsB[buf ^ 1];
#pragma unroll
            for (int j = 0; j < 2; ++j) {
                int kk = ag[j] * 4, r = ar[j];
                Asn[(kk + 0) * 68 + r] = pa[j].x;
                Asn[(kk + 1) * 68 + r] = pa[j].y;
                Asn[(kk + 2) * 68 + r] = pa[j].z;
                Asn[(kk + 3) * 68 + r] = pa[j].w;
            }
#pragma unroll
            for (int j = 0; j < 4; ++j) {
                int kk = wg[j] * 4, c = wc[j];
                Wsn[(kk + 0) * 132 + c] = pw[j].x;
                Wsn[(kk + 1) * 132 + c] = pw[j].y;
                Wsn[(kk + 2) * 132 + c] = pw[j].z;
                Wsn[(kk + 3) * 132 + c] = pw[j].w;
            }
            __syncthreads();
        }
    }

    // ---- epilogue: degree-scaled bias + relu ----
    const int colbase = tx * 4;
    float4 bw  = *(const float4*)(Wb  + colbase);
    float4 bs  = *(const float4*)(Wsb + colbase);
    float4 bt  = *(const float4*)(Wtb + colbase);

#pragma unroll
    for (int p = 0; p < 4; ++p) {
        int re = row0 + ty * 8 + 2 * p;
        if (re >= N_NODES) break;
        float2 v0 = unpack2(acc[p][0]);
        float2 v1 = unpack2(acc[p][1]);
        float2 v2 = unpack2(acc[p][2]);
        float2 v3 = unpack2(acc[p][3]);

        {
            float f1 = (float)g_d1[re];
            float f2 = (float)g_d2[re];
            float4 o;
            o.x = fmaxf(v0.x + f1 * bw.x + bs.x + f2 * bt.x, 0.f);
            o.y = fmaxf(v1.x + f1 * bw.y + bs.y + f2 * bt.y, 0.f);
            o.z = fmaxf(v2.x + f1 * bw.z + bs.z + f2 * bt.z, 0.f);
            o.w = fmaxf(v3.x + f1 * bw.w + bs.w + f2 * bt.w, 0.f);
            *(float4*)(out + (size_t)re * HIDDEN + colbase) = o;
        }
        int ro = re + 1;
        if (ro < N_NODES) {
            float f1 = (float)g_d1[ro];
            float f2 = (float)g_d2[ro];
            float4 o;
            o.x = fmaxf(v0.y + f1 * bw.x + bs.x + f2 * bt.x, 0.f);
            o.y = fmaxf(v1.y + f1 * bw.y + bs.y + f2 * bt.y, 0.f);
            o.z = fmaxf(v2.y + f1 * bw.z + bs.z + f2 * bt.z, 0.f);
            o.w = fmaxf(v3.y + f1 * bw.w + bs.w + f2 * bt.w, 0.f);
            *(float4*)(out + (size_t)ro * HIDDEN + colbase) = o;
        }
    }
}

// ---------------- launch -----------------------------------------------------
extern "C" void kernel_launch(void* const* d_in, const int* in_sizes, int n_in,
                              void* d_out, int out_size) {
    const float* h    = (const float*)d_in[0];
    const int*   esrc = (const int*)  d_in[1];
    const int*   edst = (const int*)  d_in[2];
    const float* Ww   = (const float*)d_in[3];
    const float* Wb   = (const float*)d_in[4];
    const float* Wsw  = (const float*)d_in[5];
    const float* Wsb  = (const float*)d_in[6];
    const float* Wtw  = (const float*)d_in[7];
    const float* Wtb  = (const float*)d_in[8];
    float* out = (float*)d_out;

    cudaFuncSetAttribute(gemm_kernel,
                         cudaFuncAttributeMaxDynamicSharedMemorySize, SMEM_BYTES);

    zero_kernel<<<2048, 256>>>();
    edge_kernel<<<(N_EDGES + 7) / 8, 256>>>(h, esrc, edst);
    gemm_kernel<<<(N_NODES + 63) / 64, 256, SMEM_BYTES>>>(
        h, Ww, Wb, Wsw, Wsb, Wtw, Wtb, out);
}

// round 8
// speedup vs baseline: 1.1801x; 1.0970x over previous
#include <cuda_runtime.h>
#include <stdint.h>

#define N_NODES 100000
#define N_EDGES 800000
#define HIDDEN  128

// ---------------- scratch (static device memory; no allocation) -------------
__device__ float g_S1[(size_t)N_NODES * HIDDEN];
__device__ float g_S2[(size_t)N_NODES * HIDDEN];
__device__ int   g_d1[N_NODES];
__device__ int   g_d2[N_NODES];

// ---------------- helpers ---------------------------------------------------
__device__ __forceinline__ unsigned long long pack2(float lo, float hi) {
    unsigned long long r;
    asm("mov.b64 %0, {%1, %2};" : "=l"(r) : "f"(lo), "f"(hi));
    return r;
}
__device__ __forceinline__ float2 unpack2(unsigned long long v) {
    float2 f;
    asm("mov.b64 {%0, %1}, %2;" : "=f"(f.x), "=f"(f.y) : "l"(v));
    return f;
}
__device__ __forceinline__ void fma2(unsigned long long& acc,
                                     unsigned long long a,
                                     unsigned long long b) {
    asm("fma.rn.f32x2 %0, %1, %2, %0;" : "+l"(acc) : "l"(a), "l"(b));
}

// ---------------- kernel 1: zero scratch ------------------------------------
__global__ void zero_kernel() {
    size_t tid    = (size_t)blockIdx.x * blockDim.x + threadIdx.x;
    size_t stride = (size_t)gridDim.x * blockDim.x;
    const size_t n4 = (size_t)N_NODES * HIDDEN / 4;
    float4 z = make_float4(0.f, 0.f, 0.f, 0.f);
    for (size_t j = tid; j < n4; j += stride) {
        ((float4*)g_S1)[j] = z;
        ((float4*)g_S2)[j] = z;
    }
    for (size_t j = tid; j < N_NODES; j += stride) {
        g_d1[j] = 0;
        g_d2[j] = 0;
    }
}

// ---------------- kernel 2: fused edge aggregation (one warp per edge) ------
__global__ void __launch_bounds__(256) edge_kernel(const float* __restrict__ h,
                                                   const int*   __restrict__ esrc,
                                                   const int*   __restrict__ edst) {
    int warp = (blockIdx.x * blockDim.x + threadIdx.x) >> 5;
    int lane = threadIdx.x & 31;
    if (warp >= N_EDGES) return;

    int s = esrc[warp];
    int d = edst[warp];

    float4 vd = ((const float4*)(h + (size_t)d * HIDDEN))[lane];
    float4 vs = ((const float4*)(h + (size_t)s * HIDDEN))[lane];

    atomicAdd(((float4*)(g_S1 + (size_t)s * HIDDEN)) + lane, vd);
    atomicAdd(((float4*)(g_S2 + (size_t)d * HIDDEN)) + lane, vs);

    if (lane == 0)      atomicAdd(&g_d1[s], 1);
    else if (lane == 1) atomicAdd(&g_d2[d], 1);
}

// ---------------- GEMM core (identical geometry to measured-best R3) --------
// 64 rows x 128 cols per block, 256 threads, thread tile 8 rows x 4 cols of
// f32x2 accumulators; register-prefetch over k32 chunks.
// NCHUNK chunks; source for chunk c: Alist[c>>2], k0 = (c&3)*32.

// ---- kernel 3a: self GEMM (K=128, A=h, W=Wsw); writes raw partial + Wsb ----
__global__ void __launch_bounds__(256) gemm_self_kernel(const float* __restrict__ h,
                                                        const float* __restrict__ Wsw,
                                                        const float* __restrict__ Wsb,
                                                        float* __restrict__ out) {
    __shared__ float As[32][68];
    __shared__ float Ws[32][132];

    const int tid = threadIdx.x;
    const int tx  = tid & 31;
    const int ty  = tid >> 5;
    const int row0 = blockIdx.x * 64;

    int ar[2], ag[2], arow_ok[2];
#pragma unroll
    for (int j = 0; j < 2; ++j) {
        int lin = tid + j * 256;
        ar[j] = lin >> 3; ag[j] = lin & 7;
        arow_ok[j] = (row0 + ar[j]) < N_NODES;
    }
    int wc[4], wg[4];
#pragma unroll
    for (int j = 0; j < 4; ++j) {
        int lin = tid + j * 256;
        wc[j] = lin >> 3; wg[j] = lin & 7;
    }

    unsigned long long acc[4][4];
#pragma unroll
    for (int p = 0; p < 4; ++p)
#pragma unroll
        for (int c = 0; c < 4; ++c) acc[p][c] = 0ull;

    float4 pa[2], pw[4];
#pragma unroll
    for (int j = 0; j < 2; ++j) {
        pa[j] = make_float4(0.f, 0.f, 0.f, 0.f);
        if (arow_ok[j])
            pa[j] = *(const float4*)(h + (size_t)(row0 + ar[j]) * HIDDEN + ag[j] * 4);
    }
#pragma unroll
    for (int j = 0; j < 4; ++j)
        pw[j] = *(const float4*)(Wsw + (size_t)wc[j] * HIDDEN + wg[j] * 4);

#pragma unroll 1
    for (int chunk = 0; chunk < 4; ++chunk) {
        __syncthreads();
#pragma unroll
        for (int j = 0; j < 2; ++j) {
            int kk = ag[j] * 4, r = ar[j];
            As[kk + 0][r] = pa[j].x; As[kk + 1][r] = pa[j].y;
            As[kk + 2][r] = pa[j].z; As[kk + 3][r] = pa[j].w;
        }
#pragma unroll
        for (int j = 0; j < 4; ++j) {
            int kk = wg[j] * 4, c = wc[j];
            Ws[kk + 0][c] = pw[j].x; Ws[kk + 1][c] = pw[j].y;
            Ws[kk + 2][c] = pw[j].z; Ws[kk + 3][c] = pw[j].w;
        }
        __syncthreads();

        if (chunk < 3) {
            int k0 = (chunk + 1) * 32;
#pragma unroll
            for (int j = 0; j < 2; ++j) {
                pa[j] = make_float4(0.f, 0.f, 0.f, 0.f);
                if (arow_ok[j])
                    pa[j] = *(const float4*)(h + (size_t)(row0 + ar[j]) * HIDDEN + k0 + ag[j] * 4);
            }
#pragma unroll
            for (int j = 0; j < 4; ++j)
                pw[j] = *(const float4*)(Wsw + (size_t)wc[j] * HIDDEN + k0 + wg[j] * 4);
        }

#pragma unroll
        for (int kk = 0; kk < 32; ++kk) {
            ulonglong2 a01 = *(const ulonglong2*)&As[kk][ty * 8];
            ulonglong2 a23 = *(const ulonglong2*)&As[kk][ty * 8 + 4];
            float4 w = *(const float4*)&Ws[kk][tx * 4];
            unsigned long long w0 = pack2(w.x, w.x);
            unsigned long long w1 = pack2(w.y, w.y);
            unsigned long long w2 = pack2(w.z, w.z);
            unsigned long long w3 = pack2(w.w, w.w);
            fma2(acc[0][0], a01.x, w0); fma2(acc[0][1], a01.x, w1);
            fma2(acc[0][2], a01.x, w2); fma2(acc[0][3], a01.x, w3);
            fma2(acc[1][0], a01.y, w0); fma2(acc[1][1], a01.y, w1);
            fma2(acc[1][2], a01.y, w2); fma2(acc[1][3], a01.y, w3);
            fma2(acc[2][0], a23.x, w0); fma2(acc[2][1], a23.x, w1);
            fma2(acc[2][2], a23.x, w2); fma2(acc[2][3], a23.x, w3);
            fma2(acc[3][0], a23.y, w0); fma2(acc[3][1], a23.y, w1);
            fma2(acc[3][2], a23.y, w2); fma2(acc[3][3], a23.y, w3);
        }
    }

    const int colbase = tx * 4;
    float4 bs = *(const float4*)(Wsb + colbase);
#pragma unroll
    for (int p = 0; p < 4; ++p) {
        int re = row0 + ty * 8 + 2 * p;
        if (re >= N_NODES) break;
        float2 v0 = unpack2(acc[p][0]);
        float2 v1 = unpack2(acc[p][1]);
        float2 v2 = unpack2(acc[p][2]);
        float2 v3 = unpack2(acc[p][3]);
        {
            float4 o = make_float4(v0.x + bs.x, v1.x + bs.y, v2.x + bs.z, v3.x + bs.w);
            *(float4*)(out + (size_t)re * HIDDEN + colbase) = o;
        }
        int ro = re + 1;
        if (ro < N_NODES) {
            float4 o = make_float4(v0.y + bs.x, v1.y + bs.y, v2.y + bs.z, v3.y + bs.w);
            *(float4*)(out + (size_t)ro * HIDDEN + colbase) = o;
        }
    }
}

// ---- kernel 3b: final GEMM (K=256 over S1/Ww then S2/Wtw) + partial + relu --
__global__ void __launch_bounds__(256) gemm_final_kernel(const float* __restrict__ Ww,
                                                         const float* __restrict__ Wb,
                                                         const float* __restrict__ Wtw,
                                                         const float* __restrict__ Wtb,
                                                         float* __restrict__ out) {
    __shared__ float As[32][68];
    __shared__ float Ws[32][132];

    const int tid = threadIdx.x;
    const int tx  = tid & 31;
    const int ty  = tid >> 5;
    const int row0 = blockIdx.x * 64;

    const float* Alist[2];
    Alist[0] = g_S1; Alist[1] = g_S2;
    const float* Wlist[2];
    Wlist[0] = Ww; Wlist[1] = Wtw;

    int ar[2], ag[2], arow_ok[2];
#pragma unroll
    for (int j = 0; j < 2; ++j) {
        int lin = tid + j * 256;
        ar[j] = lin >> 3; ag[j] = lin & 7;
        arow_ok[j] = (row0 + ar[j]) < N_NODES;
    }
    int wc[4], wg[4];
#pragma unroll
    for (int j = 0; j < 4; ++j) {
        int lin = tid + j * 256;
        wc[j] = lin >> 3; wg[j] = lin & 7;
    }

    unsigned long long acc[4][4];
#pragma unroll
    for (int p = 0; p < 4; ++p)
#pragma unroll
        for (int c = 0; c < 4; ++c) acc[p][c] = 0ull;

    float4 pa[2], pw[4];
#pragma unroll
    for (int j = 0; j < 2; ++j) {
        pa[j] = make_float4(0.f, 0.f, 0.f, 0.f);
        if (arow_ok[j])
            pa[j] = *(const float4*)(g_S1 + (size_t)(row0 + ar[j]) * HIDDEN + ag[j] * 4);
    }
#pragma unroll
    for (int j = 0; j < 4; ++j)
        pw[j] = *(const float4*)(Ww + (size_t)wc[j] * HIDDEN + wg[j] * 4);

#pragma unroll 1
    for (int chunk = 0; chunk < 8; ++chunk) {
        __syncthreads();
#pragma unroll
        for (int j = 0; j < 2; ++j) {
            int kk = ag[j] * 4, r = ar[j];
            As[kk + 0][r] = pa[j].x; As[kk + 1][r] = pa[j].y;
            As[kk + 2][r] = pa[j].z; As[kk + 3][r] = pa[j].w;
        }
#pragma unroll
        for (int j = 0; j < 4; ++j) {
            int kk = wg[j] * 4, c = wc[j];
            Ws[kk + 0][c] = pw[j].x; Ws[kk + 1][c] = pw[j].y;
            Ws[kk + 2][c] = pw[j].z; Ws[kk + 3][c] = pw[j].w;
        }
        __syncthreads();

        if (chunk < 7) {
            int nc   = chunk + 1;
            int sidx = nc >> 2;
            int k0   = (nc & 3) * 32;
            const float* A = Alist[sidx];
            const float* W = Wlist[sidx];
#pragma unroll
            for (int j = 0; j < 2; ++j) {
                pa[j] = make_float4(0.f, 0.f, 0.f, 0.f);
                if (arow_ok[j])
                    pa[j] = *(const float4*)(A + (size_t)(row0 + ar[j]) * HIDDEN + k0 + ag[j] * 4);
            }
#pragma unroll
            for (int j = 0; j < 4; ++j)
                pw[j] = *(const float4*)(W + (size_t)wc[j] * HIDDEN + k0 + wg[j] * 4);
        }

#pragma unroll
        for (int kk = 0; kk < 32; ++kk) {
            ulonglong2 a01 = *(const ulonglong2*)&As[kk][ty * 8];
            ulonglong2 a23 = *(const ulonglong2*)&As[kk][ty * 8 + 4];
            float4 w = *(const float4*)&Ws[kk][tx * 4];
            unsigned long long w0 = pack2(w.x, w.x);
            unsigned long long w1 = pack2(w.y, w.y);
            unsigned long long w2 = pack2(w.z, w.z);
            unsigned long long w3 = pack2(w.w, w.w);
            fma2(acc[0][0], a01.x, w0); fma2(acc[0][1], a01.x, w1);
            fma2(acc[0][2], a01.x, w2); fma2(acc[0][3], a01.x, w3);
            fma2(acc[1][0], a01.y, w0); fma2(acc[1][1], a01.y, w1);
            fma2(acc[1][2], a01.y, w2); fma2(acc[1][3], a01.y, w3);
            fma2(acc[2][0], a23.x, w0); fma2(acc[2][1], a23.x, w1);
            fma2(acc[2][2], a23.x, w2); fma2(acc[2][3], a23.x, w3);
            fma2(acc[3][0], a23.y, w0); fma2(acc[3][1], a23.y, w1);
            fma2(acc[3][2], a23.y, w2); fma2(acc[3][3], a23.y, w3);
        }
    }

    const int colbase = tx * 4;
    float4 bw = *(const float4*)(Wb  + colbase);
    float4 bt = *(const float4*)(Wtb + colbase);

#pragma unroll
    for (int p = 0; p < 4; ++p) {
        int re = row0 + ty * 8 + 2 * p;
        if (re >= N_NODES) break;
        float2 v0 = unpack2(acc[p][0]);
        float2 v1 = unpack2(acc[p][1]);
        float2 v2 = unpack2(acc[p][2]);
        float2 v3 = unpack2(acc[p][3]);
        {
            float f1 = (float)g_d1[re];
            float f2 = (float)g_d2[re];
            float4 pv = *(const float4*)(out + (size_t)re * HIDDEN + colbase);
            float4 o;
            o.x = fmaxf(pv.x + v0.x + f1 * bw.x + f2 * bt.x, 0.f);
            o.y = fmaxf(pv.y + v1.x + f1 * bw.y + f2 * bt.y, 0.f);
            o.z = fmaxf(pv.z + v2.x + f1 * bw.z + f2 * bt.z, 0.f);
            o.w = fmaxf(pv.w + v3.x + f1 * bw.w + f2 * bt.w, 0.f);
            *(float4*)(out + (size_t)re * HIDDEN + colbase) = o;
        }
        int ro = re + 1;
        if (ro < N_NODES) {
            float f1 = (float)g_d1[ro];
            float f2 = (float)g_d2[ro];
            float4 pv = *(const float4*)(out + (size_t)ro * HIDDEN + colbase);
            float4 o;
            o.x = fmaxf(pv.x + v0.y + f1 * bw.x + f2 * bt.x, 0.f);
            o.y = fmaxf(pv.y + v1.y + f1 * bw.y + f2 * bt.y, 0.f);
            o.z = fmaxf(pv.z + v2.y + f1 * bw.z + f2 * bt.z, 0.f);
            o.w = fmaxf(pv.w + v3.y + f1 * bw.w + f2 * bt.w, 0.f);
            *(float4*)(out + (size_t)ro * HIDDEN + colbase) = o;
        }
    }
}

// ---------------- launch: fork-join overlap ----------------------------------
extern "C" void kernel_launch(void* const* d_in, const int* in_sizes, int n_in,
                              void* d_out, int out_size) {
    const float* h    = (const float*)d_in[0];
    const int*   esrc = (const int*)  d_in[1];
    const int*   edst = (const int*)  d_in[2];
    const float* Ww   = (const float*)d_in[3];
    const float* Wb   = (const float*)d_in[4];
    const float* Wsw  = (const float*)d_in[5];
    const float* Wsb  = (const float*)d_in[6];
    const float* Wtw  = (const float*)d_in[7];
    const float* Wtb  = (const float*)d_in[8];
    float* out = (float*)d_out;

    // one-time resource creation (first call = uncaptured correctness run)
    static cudaStream_t s_side = nullptr;
    static cudaEvent_t  ev_fork = nullptr, ev_join = nullptr;
    if (s_side == nullptr) {
        cudaStreamCreateWithFlags(&s_side, cudaStreamNonBlocking);
        cudaEventCreateWithFlags(&ev_fork, cudaEventDisableTiming);
        cudaEventCreateWithFlags(&ev_join, cudaEventDisableTiming);
    }

    // fork: side stream runs the self-term GEMM (depends only on input h)
    cudaEventRecord(ev_fork, 0);
    cudaStreamWaitEvent(s_side, ev_fork, 0);
    gemm_self_kernel<<<(N_NODES + 63) / 64, 256, 0, s_side>>>(h, Wsw, Wsb, out);

    // main stream: zero scratch, then edge aggregation
    zero_kernel<<<2048, 256>>>();
    edge_kernel<<<(N_EDGES + 7) / 8, 256>>>(h, esrc, edst);

    // join, then final GEMM over S1/S2 + partial + relu
    cudaEventRecord(ev_join, s_side);
    cudaStreamWaitEvent(0, ev_join, 0);
    gemm_final_kernel<<<(N_NODES + 63) / 64, 256>>>(Ww, Wb, Wtw, Wtb, out);
}

// round 10
// speedup vs baseline: 1.2300x; 1.0423x over previous
#include <cuda_runtime.h>
#include <stdint.h>

#define N_NODES 100000
#define N_EDGES 800000
#define HIDDEN  128

// ---------------- scratch (static device memory; no allocation) -------------
__device__ float g_S1[(size_t)N_NODES * HIDDEN];   // sum over edges (i,j) of h[j], indexed by i
__device__ float g_S2[(size_t)N_NODES * HIDDEN];   // sum over edges (i,j) of h[i], indexed by j
__device__ int   g_d1[N_NODES];                    // out-degree
__device__ int   g_d2[N_NODES];                    // in-degree

// ---------------- helpers ---------------------------------------------------
__device__ __forceinline__ unsigned long long pack2(float lo, float hi) {
    unsigned long long r;
    asm("mov.b64 %0, {%1, %2};" : "=l"(r) : "f"(lo), "f"(hi));
    return r;
}
__device__ __forceinline__ float2 unpack2(unsigned long long v) {
    float2 f;
    asm("mov.b64 {%0, %1}, %2;" : "=f"(f.x), "=f"(f.y) : "l"(v));
    return f;
}
__device__ __forceinline__ void fma2(unsigned long long& acc,
                                     unsigned long long a,
                                     unsigned long long b) {
    asm("fma.rn.f32x2 %0, %1, %2, %0;" : "+l"(acc) : "l"(a), "l"(b));
}

// ---------------- kernel 1: zero scratch ------------------------------------
__global__ void zero_kernel() {
    size_t tid    = (size_t)blockIdx.x * blockDim.x + threadIdx.x;
    size_t stride = (size_t)gridDim.x * blockDim.x;
    const size_t n4 = (size_t)N_NODES * HIDDEN / 4;
    float4 z = make_float4(0.f, 0.f, 0.f, 0.f);
    for (size_t j = tid; j < n4; j += stride) {
        ((float4*)g_S1)[j] = z;
        ((float4*)g_S2)[j] = z;
    }
    for (size_t j = tid; j < N_NODES; j += stride) {
        g_d1[j] = 0;
        g_d2[j] = 0;
    }
}

// ---------------- kernel 2: fused edge aggregation (one warp per edge) ------
__global__ void __launch_bounds__(256) edge_kernel(const float* __restrict__ h,
                                                   const int*   __restrict__ esrc,
                                                   const int*   __restrict__ edst) {
    int warp = (blockIdx.x * blockDim.x + threadIdx.x) >> 5;
    int lane = threadIdx.x & 31;
    if (warp >= N_EDGES) return;

    int s = esrc[warp];
    int d = edst[warp];

    float4 vd = ((const float4*)(h + (size_t)d * HIDDEN))[lane];
    float4 vs = ((const float4*)(h + (size_t)s * HIDDEN))[lane];

    atomicAdd(((float4*)(g_S1 + (size_t)s * HIDDEN)) + lane, vd);
    atomicAdd(((float4*)(g_S2 + (size_t)d * HIDDEN)) + lane, vs);

    if (lane == 0)      atomicAdd(&g_d1[s], 1);
    else if (lane == 1) atomicAdd(&g_d2[d], 1);
}

// ---------------- kernel 3: fused GEMM + bias + relu ------------------------
// out[i] = relu( S1[i]@Ww^T + d1[i]*Wb + h[i]@Wsw^T + Wsb + S2[i]@Wtw^T + d2[i]*Wtb )
// 64 rows x 128 cols per block, 256 threads, thread tile 8 rows x 4 cols of
// f32x2 accumulators. Plain stage->sync->compute core (measured 247us at
// 2 CTAs/SM); this version caps regs at 85 for 3 CTAs/SM (occ 24% -> 36%).
__global__ void __launch_bounds__(256, 3)
gemm_kernel(const float* __restrict__ h,
            const float* __restrict__ Ww,
            const float* __restrict__ Wb,
            const float* __restrict__ Wsw,
            const float* __restrict__ Wsb,
            const float* __restrict__ Wtw,
            const float* __restrict__ Wtb,
            float* __restrict__ out) {
    __shared__ float As[32][68];    // [k][row]
    __shared__ float Ws[32][132];   // [k][col]

    const int tid = threadIdx.x;
    const int tx  = tid & 31;       // col group: cols tx*4 .. tx*4+3
    const int ty  = tid >> 5;       // row group: rows ty*8 .. ty*8+7
    const int row0 = blockIdx.x * 64;

    unsigned long long acc[4][4];
#pragma unroll
    for (int p = 0; p < 4; ++p)
#pragma unroll
        for (int c = 0; c < 4; ++c) acc[p][c] = 0ull;

#pragma unroll 1
    for (int chunk = 0; chunk < 12; ++chunk) {
        const int sidx = chunk >> 2;          // 0: S1/Ww, 1: h/Wsw, 2: S2/Wtw
        const int k0   = (chunk & 3) * 32;
        const float* A = (sidx == 0) ? g_S1 : (sidx == 1) ? h : g_S2;
        const float* W = (sidx == 0) ? Ww   : (sidx == 1) ? Wsw : Wtw;

        __syncthreads();
        // load A tile: 64 rows x 32 k  (512 float4, 2 per thread)
#pragma unroll
        for (int j = 0; j < 2; ++j) {
            int lin = tid + j * 256;          // 0..511
            int r   = lin >> 3;               // 0..63
            int g   = lin & 7;                // float4 group in k
            float4 v = make_float4(0.f, 0.f, 0.f, 0.f);
            int row = row0 + r;
            if (row < N_NODES)
                v = *(const float4*)(A + (size_t)row * HIDDEN + k0 + g * 4);
            int kk = g * 4;
            As[kk + 0][r] = v.x;
            As[kk + 1][r] = v.y;
            As[kk + 2][r] = v.z;
            As[kk + 3][r] = v.w;
        }
        // load W tile: 128 cols x 32 k (1024 float4, 4 per thread)
#pragma unroll
        for (int j = 0; j < 4; ++j) {
            int lin = tid + j * 256;          // 0..1023
            int c   = lin >> 3;               // 0..127
            int g   = lin & 7;
            float4 v = *(const float4*)(W + (size_t)c * HIDDEN + k0 + g * 4);
            int kk = g * 4;
            Ws[kk + 0][c] = v.x;
            Ws[kk + 1][c] = v.y;
            Ws[kk + 2][c] = v.z;
            Ws[kk + 3][c] = v.w;
        }
        __syncthreads();

#pragma unroll
        for (int kk = 0; kk < 32; ++kk) {
            ulonglong2 a01 = *(const ulonglong2*)&As[kk][ty * 8];
            ulonglong2 a23 = *(const ulonglong2*)&As[kk][ty * 8 + 4];
            float4 w = *(const float4*)&Ws[kk][tx * 4];
            unsigned long long w0 = pack2(w.x, w.x);
            unsigned long long w1 = pack2(w.y, w.y);
            unsigned long long w2 = pack2(w.z, w.z);
            unsigned long long w3 = pack2(w.w, w.w);

            fma2(acc[0][0], a01.x, w0); fma2(acc[0][1], a01.x, w1);
            fma2(acc[0][2], a01.x, w2); fma2(acc[0][3], a01.x, w3);
            fma2(acc[1][0], a01.y, w0); fma2(acc[1][1], a01.y, w1);
            fma2(acc[1][2], a01.y, w2); fma2(acc[1][3], a01.y, w3);
            fma2(acc[2][0], a23.x, w0); fma2(acc[2][1], a23.x, w1);
            fma2(acc[2][2], a23.x, w2); fma2(acc[2][3], a23.x, w3);
            fma2(acc[3][0], a23.y, w0); fma2(acc[3][1], a23.y, w1);
            fma2(acc[3][2], a23.y, w2); fma2(acc[3][3], a23.y, w3);
        }
    }

    // epilogue: degree-scaled bias + relu, float4 stores
    const int colbase = tx * 4;
    float4 bw  = *(const float4*)(Wb  + colbase);
    float4 bs  = *(const float4*)(Wsb + colbase);
    float4 bt  = *(const float4*)(Wtb + colbase);

#pragma unroll
    for (int p = 0; p < 4; ++p) {
        int re = row0 + ty * 8 + 2 * p;
        if (re >= N_NODES) break;
        float2 v0 = unpack2(acc[p][0]);
        float2 v1 = unpack2(acc[p][1]);
        float2 v2 = unpack2(acc[p][2]);
        float2 v3 = unpack2(acc[p][3]);

        {
            float f1 = (float)g_d1[re];
            float f2 = (float)g_d2[re];
            float4 o;
            o.x = fmaxf(v0.x + f1 * bw.x + bs.x + f2 * bt.x, 0.f);
            o.y = fmaxf(v1.x + f1 * bw.y + bs.y + f2 * bt.y, 0.f);
            o.z = fmaxf(v2.x + f1 * bw.z + bs.z + f2 * bt.z, 0.f);
            o.w = fmaxf(v3.x + f1 * bw.w + bs.w + f2 * bt.w, 0.f);
            *(float4*)(out + (size_t)re * HIDDEN + colbase) = o;
        }
        int ro = re + 1;
        if (ro < N_NODES) {
            float f1 = (float)g_d1[ro];
            float f2 = (float)g_d2[ro];
            float4 o;
            o.x = fmaxf(v0.y + f1 * bw.x + bs.x + f2 * bt.x, 0.f);
            o.y = fmaxf(v1.y + f1 * bw.y + bs.y + f2 * bt.y, 0.f);
            o.z = fmaxf(v2.y + f1 * bw.z + bs.z + f2 * bt.z, 0.f);
            o.w = fmaxf(v3.y + f1 * bw.w + bs.w + f2 * bt.w, 0.f);
            *(float4*)(out + (size_t)ro * HIDDEN + colbase) = o;
        }
    }
}

// ---------------- launch -----------------------------------------------------
extern "C" void kernel_launch(void* const* d_in, const int* in_sizes, int n_in,
                              void* d_out, int out_size) {
    const float* h    = (const float*)d_in[0];
    const int*   esrc = (const int*)  d_in[1];
    const int*   edst = (const int*)  d_in[2];
    const float* Ww   = (const float*)d_in[3];
    const float* Wb   = (const float*)d_in[4];
    const float* Wsw  = (const float*)d_in[5];
    const float* Wsb  = (const float*)d_in[6];
    const float* Wtw  = (const float*)d_in[7];
    const float* Wtb  = (const float*)d_in[8];
    float* out = (float*)d_out;

    zero_kernel<<<2048, 256>>>();
    edge_kernel<<<(N_EDGES + 7) / 8, 256>>>(h, esrc, edst);
    gemm_kernel<<<(N_NODES + 63) / 64, 256>>>(h, Ww, Wb, Wsw, Wsb, Wtw, Wtb, out);
}